// round 3
// baseline (speedup 1.0000x reference)
#include <cuda_runtime.h>
#include <cstdint>

// Problem constants
#define BB  4
#define SS  2048
#define DD  1024
#define HH  16
#define DK  64
#define MM  (BB * SS)        // 8192 rows for projection GEMMs

// ---------------------------------------------------------------------------
// Scratch (device globals; no allocation allowed)
// ---------------------------------------------------------------------------
__device__ float g_q[(size_t)BB * HH * SS * DK];   // (b,h,s,d) split-head
__device__ float g_k[(size_t)BB * HH * SS * DK];
__device__ float g_v[(size_t)BB * HH * SS * DK];
__device__ float g_att[(size_t)BB * SS * DD];      // concat-head (b,s,h*64+d)

// ---------------------------------------------------------------------------
// SGEMM: C[m,n] = sum_k A[m,k] * W[n,k] + bias[n]
// A: row-major MxK, W: row-major NxK (so this is X @ W^T), fp32.
// Tile 128x128x8, 256 threads, 8x8 microtile.
// split_mode==1: write into split-head layout: n -> (d = n>>4, h = n&15),
//                dst[((b*16+h)*2048+s)*64 + d], with m -> (b = m>>11, s = m&2047)
// ---------------------------------------------------------------------------
#define GBM 128
#define GBN 128
#define GBK 8

__global__ __launch_bounds__(256) void sgemm_nt_kernel(
    const float* __restrict__ A, const float* __restrict__ W,
    const float* __restrict__ bias, float* __restrict__ C,
    int M, int N, int K, int split_mode)
{
    __shared__ float As[GBK][GBM];
    __shared__ float Bs[GBK][GBN];

    const int tid  = threadIdx.x;
    const int m0   = blockIdx.y * GBM;
    const int n0   = blockIdx.x * GBN;
    const int lrow = tid >> 1;           // 0..127
    const int lcol = (tid & 1) * 4;      // 0 or 4
    const int ty   = tid >> 4;           // 0..15 (rows)
    const int tx   = tid & 15;           // 0..15 (cols)

    float acc[8][8];
#pragma unroll
    for (int i = 0; i < 8; i++)
#pragma unroll
        for (int j = 0; j < 8; j++) acc[i][j] = 0.0f;

    const float* Aptr = A + (size_t)(m0 + lrow) * K + lcol;
    const float* Wptr = W + (size_t)(n0 + lrow) * K + lcol;

    for (int k0 = 0; k0 < K; k0 += GBK) {
        float4 av = *(const float4*)(Aptr + k0);
        float4 bv = *(const float4*)(Wptr + k0);
        As[lcol + 0][lrow] = av.x;
        As[lcol + 1][lrow] = av.y;
        As[lcol + 2][lrow] = av.z;
        As[lcol + 3][lrow] = av.w;
        Bs[lcol + 0][lrow] = bv.x;
        Bs[lcol + 1][lrow] = bv.y;
        Bs[lcol + 2][lrow] = bv.z;
        Bs[lcol + 3][lrow] = bv.w;
        __syncthreads();

#pragma unroll
        for (int k = 0; k < GBK; k++) {
            float a[8], b[8];
            float4 a0 = *(const float4*)&As[k][ty * 8];
            float4 a1 = *(const float4*)&As[k][ty * 8 + 4];
            float4 b0 = *(const float4*)&Bs[k][tx * 8];
            float4 b1 = *(const float4*)&Bs[k][tx * 8 + 4];
            a[0]=a0.x; a[1]=a0.y; a[2]=a0.z; a[3]=a0.w;
            a[4]=a1.x; a[5]=a1.y; a[6]=a1.z; a[7]=a1.w;
            b[0]=b0.x; b[1]=b0.y; b[2]=b0.z; b[3]=b0.w;
            b[4]=b1.x; b[5]=b1.y; b[6]=b1.z; b[7]=b1.w;
#pragma unroll
            for (int i = 0; i < 8; i++)
#pragma unroll
                for (int j = 0; j < 8; j++)
                    acc[i][j] = fmaf(a[i], b[j], acc[i][j]);
        }
        __syncthreads();
    }

    // Epilogue
#pragma unroll
    for (int i = 0; i < 8; i++) {
        const int m = m0 + ty * 8 + i;
#pragma unroll
        for (int j = 0; j < 8; j++) {
            const int n = n0 + tx * 8 + j;
            float v = acc[i][j] + bias[n];
            if (split_mode) {
                const int b = m >> 11, s = m & 2047;
                const int d = n >> 4,  h = n & 15;
                C[((((size_t)b * HH + h) * SS + s) << 6) + d] = v;
            } else {
                C[(size_t)m * N + n] = v;
            }
        }
    }
}

// ---------------------------------------------------------------------------
// Flash attention (fp32, causal). One CTA = 64 queries of one (b,h).
// Q/K/V in (b,h,s,d) layout, d contiguous (DK=64).
// Output written directly in concat layout: Out[(b*S+s)*1024 + h*64 + d].
// 256 threads; microtile 4 rows x 4 cols. K stored d-major with +1 pad.
// ---------------------------------------------------------------------------
#define FA_SM_FLOATS (64*64 + 64*65 + 64*64 + 64*64)   // Qs, Kst, Vs, Ps
#define FA_SM_BYTES  (FA_SM_FLOATS * 4)

__global__ __launch_bounds__(256) void flash_kernel(
    const float* __restrict__ Qg, const float* __restrict__ Kg,
    const float* __restrict__ Vg, float* __restrict__ Out)
{
    extern __shared__ float sm[];
    float* Qs  = sm;                       // [64][64] row-major (m,d)
    float* Kst = sm + 64 * 64;             // [64][65]  (d, n) padded
    float* Vs  = Kst + 64 * 65;            // [64][64]  (n, d)
    float* Ps  = Vs + 64 * 64;             // [64][64]  (m, n)

    const int tid = threadIdx.x;
    const int qb  = blockIdx.x;            // query block 0..31
    const int bh  = blockIdx.y;            // 0..63
    const int b   = bh >> 4, h = bh & 15;
    const int ty  = tid >> 4, tx = tid & 15;
    const int ty4 = ty * 4,  tx4 = tx * 4;

    const float* q = Qg + (size_t)bh * SS * DK;
    const float* k = Kg + (size_t)bh * SS * DK;
    const float* v = Vg + (size_t)bh * SS * DK;

    // Load Q tile (coalesced: 2 full rows per warp instruction)
    for (int idx = tid; idx < 64 * 16; idx += 256) {
        const int r = idx >> 4, c = (idx & 15) << 2;
        *(float4*)&Qs[r * 64 + c] =
            *(const float4*)&q[(size_t)(qb * 64 + r) * DK + c];
    }

    const float NEG = -1e30f;
    float m_i[4], l_i[4], o[4][4];
#pragma unroll
    for (int i = 0; i < 4; i++) {
        m_i[i] = NEG; l_i[i] = 0.0f;
#pragma unroll
        for (int j = 0; j < 4; j++) o[i][j] = 0.0f;
    }

    for (int jb = 0; jb <= qb; jb++) {
        __syncthreads();   // protect Kst/Vs/Ps from previous iteration readers
        // Load K (transposed to d-major, padded) and V (row-major)
        for (int idx = tid; idx < 64 * 16; idx += 256) {
            const int r = idx >> 4, c = (idx & 15) << 2;
            float4 kv = *(const float4*)&k[(size_t)(jb * 64 + r) * DK + c];
            Kst[(c + 0) * 65 + r] = kv.x;
            Kst[(c + 1) * 65 + r] = kv.y;
            Kst[(c + 2) * 65 + r] = kv.z;
            Kst[(c + 3) * 65 + r] = kv.w;
            *(float4*)&Vs[r * 64 + c] =
                *(const float4*)&v[(size_t)(jb * 64 + r) * DK + c];
        }
        __syncthreads();

        // S = scale * Q K^T  (64x64x64)
        float sv[4][4];
#pragma unroll
        for (int i = 0; i < 4; i++)
#pragma unroll
            for (int j = 0; j < 4; j++) sv[i][j] = 0.0f;

#pragma unroll 8
        for (int d = 0; d < 64; d++) {
            float a0 = Qs[(ty4 + 0) * 64 + d];
            float a1 = Qs[(ty4 + 1) * 64 + d];
            float a2 = Qs[(ty4 + 2) * 64 + d];
            float a3 = Qs[(ty4 + 3) * 64 + d];
            float b0 = Kst[d * 65 + tx4 + 0];
            float b1 = Kst[d * 65 + tx4 + 1];
            float b2 = Kst[d * 65 + tx4 + 2];
            float b3 = Kst[d * 65 + tx4 + 3];
            sv[0][0] = fmaf(a0, b0, sv[0][0]); sv[0][1] = fmaf(a0, b1, sv[0][1]);
            sv[0][2] = fmaf(a0, b2, sv[0][2]); sv[0][3] = fmaf(a0, b3, sv[0][3]);
            sv[1][0] = fmaf(a1, b0, sv[1][0]); sv[1][1] = fmaf(a1, b1, sv[1][1]);
            sv[1][2] = fmaf(a1, b2, sv[1][2]); sv[1][3] = fmaf(a1, b3, sv[1][3]);
            sv[2][0] = fmaf(a2, b0, sv[2][0]); sv[2][1] = fmaf(a2, b1, sv[2][1]);
            sv[2][2] = fmaf(a2, b2, sv[2][2]); sv[2][3] = fmaf(a2, b3, sv[2][3]);
            sv[3][0] = fmaf(a3, b0, sv[3][0]); sv[3][1] = fmaf(a3, b1, sv[3][1]);
            sv[3][2] = fmaf(a3, b2, sv[3][2]); sv[3][3] = fmaf(a3, b3, sv[3][3]);
        }

        const float scale = 0.125f;   // 1/sqrt(64)
        const bool diag = (jb == qb);
        const int gm0 = qb * 64 + ty4;
        const int gn0 = jb * 64 + tx4;

        // mask + online softmax update
#pragma unroll
        for (int i = 0; i < 4; i++) {
#pragma unroll
            for (int j = 0; j < 4; j++) {
                float val = sv[i][j] * scale;
                if (diag && (gn0 + j > gm0 + i)) val = NEG;
                sv[i][j] = val;
            }
            float r = fmaxf(fmaxf(sv[i][0], sv[i][1]), fmaxf(sv[i][2], sv[i][3]));
            r = fmaxf(r, __shfl_xor_sync(0xffffffffu, r, 8));
            r = fmaxf(r, __shfl_xor_sync(0xffffffffu, r, 4));
            r = fmaxf(r, __shfl_xor_sync(0xffffffffu, r, 2));
            r = fmaxf(r, __shfl_xor_sync(0xffffffffu, r, 1));
            const float mn = fmaxf(m_i[i], r);
            const float corr = __expf(m_i[i] - mn);
            float rs = 0.0f;
#pragma unroll
            for (int j = 0; j < 4; j++) {
                float p = __expf(sv[i][j] - mn);
                sv[i][j] = p;
                rs += p;
            }
            rs += __shfl_xor_sync(0xffffffffu, rs, 8);
            rs += __shfl_xor_sync(0xffffffffu, rs, 4);
            rs += __shfl_xor_sync(0xffffffffu, rs, 2);
            rs += __shfl_xor_sync(0xffffffffu, rs, 1);
            l_i[i] = l_i[i] * corr + rs;
            m_i[i] = mn;
#pragma unroll
            for (int j = 0; j < 4; j++) o[i][j] *= corr;
            *(float4*)&Ps[(ty4 + i) * 64 + tx4] =
                make_float4(sv[i][0], sv[i][1], sv[i][2], sv[i][3]);
        }
        __syncthreads();

        // O += P @ V  (64x64x64)
#pragma unroll 8
        for (int n = 0; n < 64; n++) {
            float4 bb = *(const float4*)&Vs[n * 64 + tx4];
            float a0 = Ps[(ty4 + 0) * 64 + n];
            float a1 = Ps[(ty4 + 1) * 64 + n];
            float a2 = Ps[(ty4 + 2) * 64 + n];
            float a3 = Ps[(ty4 + 3) * 64 + n];
            o[0][0] = fmaf(a0, bb.x, o[0][0]); o[0][1] = fmaf(a0, bb.y, o[0][1]);
            o[0][2] = fmaf(a0, bb.z, o[0][2]); o[0][3] = fmaf(a0, bb.w, o[0][3]);
            o[1][0] = fmaf(a1, bb.x, o[1][0]); o[1][1] = fmaf(a1, bb.y, o[1][1]);
            o[1][2] = fmaf(a1, bb.z, o[1][2]); o[1][3] = fmaf(a1, bb.w, o[1][3]);
            o[2][0] = fmaf(a2, bb.x, o[2][0]); o[2][1] = fmaf(a2, bb.y, o[2][1]);
            o[2][2] = fmaf(a2, bb.z, o[2][2]); o[2][3] = fmaf(a2, bb.w, o[2][3]);
            o[3][0] = fmaf(a3, bb.x, o[3][0]); o[3][1] = fmaf(a3, bb.y, o[3][1]);
            o[3][2] = fmaf(a3, bb.z, o[3][2]); o[3][3] = fmaf(a3, bb.w, o[3][3]);
        }
    }

    // Normalize + write in concat-head layout
#pragma unroll
    for (int i = 0; i < 4; i++) {
        const float inv = 1.0f / l_i[i];
        const int gm = qb * 64 + ty4 + i;
        float4 r = make_float4(o[i][0] * inv, o[i][1] * inv,
                               o[i][2] * inv, o[i][3] * inv);
        *(float4*)&Out[(((size_t)(b * SS + gm)) << 10) + h * 64 + tx4] = r;
    }
}

// ---------------------------------------------------------------------------
// Launch
// ---------------------------------------------------------------------------
extern "C" void kernel_launch(void* const* d_in, const int* in_sizes, int n_in,
                              void* d_out, int out_size)
{
    const float* query = (const float*)d_in[0];
    const float* key   = (const float*)d_in[1];
    const float* value = (const float*)d_in[2];
    // d_in[3] = mask (known causal; handled analytically)
    const float* w_q = (const float*)d_in[4];
    const float* b_q = (const float*)d_in[5];
    const float* w_k = (const float*)d_in[6];
    const float* b_k = (const float*)d_in[7];
    const float* w_v = (const float*)d_in[8];
    const float* b_v = (const float*)d_in[9];
    const float* w_o = (const float*)d_in[10];
    const float* b_o = (const float*)d_in[11];
    float* out = (float*)d_out;

    float *pq, *pk, *pv, *pa;
    cudaGetSymbolAddress((void**)&pq, g_q);
    cudaGetSymbolAddress((void**)&pk, g_k);
    cudaGetSymbolAddress((void**)&pv, g_v);
    cudaGetSymbolAddress((void**)&pa, g_att);

    cudaFuncSetAttribute(flash_kernel,
                         cudaFuncAttributeMaxDynamicSharedMemorySize,
                         FA_SM_BYTES);

    const dim3 gg(DD / GBN, MM / GBM);   // (8, 64)
    sgemm_nt_kernel<<<gg, 256>>>(query, w_q, b_q, pq, MM, DD, DD, 1);
    sgemm_nt_kernel<<<gg, 256>>>(key,   w_k, b_k, pk, MM, DD, DD, 1);
    sgemm_nt_kernel<<<gg, 256>>>(value, w_v, b_v, pv, MM, DD, DD, 1);

    flash_kernel<<<dim3(SS / 64, BB * HH), 256, FA_SM_BYTES>>>(pq, pk, pv, pa);

    sgemm_nt_kernel<<<gg, 256>>>(pa, w_o, b_o, out, MM, DD, DD, 0);
}

// round 7
// speedup vs baseline: 1.3160x; 1.3160x over previous
#include <cuda_runtime.h>
#include <cstdint>

// Problem constants
#define BB  4
#define SS  2048
#define DD  1024
#define HH  16
#define DK  64
#define MM  (BB * SS)        // 8192 rows for projection GEMMs

// ---------------------------------------------------------------------------
// Scratch (device globals; no allocation allowed)
// ---------------------------------------------------------------------------
__device__ float g_q[(size_t)BB * HH * SS * DK];   // (b,h,s,d) split-head
__device__ float g_k[(size_t)BB * HH * SS * DK];
__device__ float g_v[(size_t)BB * HH * SS * DK];
__device__ float g_att[(size_t)BB * SS * DD];      // concat-head (b,s,h*64+d)

// ---------------------------------------------------------------------------
// tf32 helpers
// ---------------------------------------------------------------------------
__device__ __forceinline__ uint32_t f2tf32(float x) {
    uint32_t r;
    asm("cvt.rna.tf32.f32 %0, %1;" : "=r"(r) : "f"(x));
    return r;
}

__device__ __forceinline__ void mma_tf32(float* c,
    uint32_t a0, uint32_t a1, uint32_t a2, uint32_t a3,
    uint32_t b0, uint32_t b1)
{
    asm volatile(
        "mma.sync.aligned.m16n8k8.row.col.f32.tf32.tf32.f32 "
        "{%0,%1,%2,%3}, {%4,%5,%6,%7}, {%8,%9}, {%0,%1,%2,%3};\n"
        : "+f"(c[0]), "+f"(c[1]), "+f"(c[2]), "+f"(c[3])
        : "r"(a0), "r"(a1), "r"(a2), "r"(a3), "r"(b0), "r"(b1));
}

// ---------------------------------------------------------------------------
// tf32 tensor-core GEMM: C[m,n] = sum_k A[m,k]*W[n,k] + bias[n]
// CTA tile 128x128x32, 256 threads = 8 warps (2 m x 4 n), warp tile 64x32.
// mma m16n8k8 tf32, fp32 accumulate.
// Smem layout: row stride 40 (pad 8), k permuted within groups of 8 so that
// fragment pairs {k, k+4} are adjacent -> conflict-free LDS.64.
// split_mode==1: n -> (d=n>>4, h=n&15), dst[((b*16+h)*2048+s)*64+d]
// ---------------------------------------------------------------------------
#define TSTRIDE 40

__global__ __launch_bounds__(256) void tgemm_nt_kernel(
    const float* __restrict__ A, const float* __restrict__ W,
    const float* __restrict__ bias, float* __restrict__ C,
    int M, int N, int K, int split_mode)
{
    __shared__ uint32_t As[128 * TSTRIDE];
    __shared__ uint32_t Bs[128 * TSTRIDE];

    const int tid    = threadIdx.x;
    const int lane   = tid & 31;
    const int warp   = tid >> 5;
    const int warp_m = warp >> 2;        // 0..1  -> 64 rows each
    const int warp_n = warp & 3;         // 0..3  -> 32 cols each
    const int m0     = blockIdx.y * 128;
    const int n0     = blockIdx.x * 128;

    float acc[4][4][4];
#pragma unroll
    for (int i = 0; i < 4; i++)
#pragma unroll
        for (int j = 0; j < 4; j++)
#pragma unroll
            for (int r = 0; r < 4; r++) acc[i][j][r] = 0.0f;

    const int g_row = tid >> 3;            // 0..31 step rows (x4 iters)
    const int g_kc  = (tid & 7) << 2;      // 0,4,...,28

    for (int k0 = 0; k0 < K; k0 += 32) {
        // ---- load A and B tiles (128x32 each) with tf32 convert + k-perm ----
#pragma unroll
        for (int i = 0; i < 4; i++) {
            const int row = g_row + i * 32;
            float4 va = *(const float4*)(A + (size_t)(m0 + row) * K + k0 + g_kc);
            float4 vb = *(const float4*)(W + (size_t)(n0 + row) * K + k0 + g_kc);
            const float av[4] = {va.x, va.y, va.z, va.w};
            const float bv[4] = {vb.x, vb.y, vb.z, vb.w};
#pragma unroll
            for (int j = 0; j < 4; j++) {
                const int k    = g_kc + j;
                const int colp = (k & ~7) + ((k & 3) << 1) + ((k >> 2) & 1);
                As[row * TSTRIDE + colp] = f2tf32(av[j]);
                Bs[row * TSTRIDE + colp] = f2tf32(bv[j]);
            }
        }
        __syncthreads();

        const int a_base = (warp_m * 64 + (lane >> 2)) * TSTRIDE + ((lane & 3) << 1);
        const int b_base = (warp_n * 32 + (lane >> 2)) * TSTRIDE + ((lane & 3) << 1);

#pragma unroll
        for (int kk = 0; kk < 4; kk++) {
            uint32_t af[4][4];
            uint32_t bf[4][2];
#pragma unroll
            for (int mf = 0; mf < 4; mf++) {
                const uint2 a02 = *(const uint2*)&As[a_base + mf * 16 * TSTRIDE + kk * 8];
                const uint2 a13 = *(const uint2*)&As[a_base + (mf * 16 + 8) * TSTRIDE + kk * 8];
                af[mf][0] = a02.x; af[mf][1] = a13.x;
                af[mf][2] = a02.y; af[mf][3] = a13.y;
            }
#pragma unroll
            for (int nf = 0; nf < 4; nf++) {
                const uint2 b01 = *(const uint2*)&Bs[b_base + nf * 8 * TSTRIDE + kk * 8];
                bf[nf][0] = b01.x; bf[nf][1] = b01.y;
            }
#pragma unroll
            for (int mf = 0; mf < 4; mf++)
#pragma unroll
                for (int nf = 0; nf < 4; nf++)
                    mma_tf32(acc[mf][nf],
                             af[mf][0], af[mf][1], af[mf][2], af[mf][3],
                             bf[nf][0], bf[nf][1]);
        }
        __syncthreads();
    }

    // ---- epilogue ----
    const int m_lo0 = m0 + warp_m * 64 + (lane >> 2);
    const int n_b0  = n0 + warp_n * 32 + ((lane & 3) << 1);
#pragma unroll
    for (int mf = 0; mf < 4; mf++) {
#pragma unroll
        for (int nf = 0; nf < 4; nf++) {
            const int m_lo = m_lo0 + mf * 16;
            const int m_hi = m_lo + 8;
            const int nb   = n_b0 + nf * 8;
            const float v00 = acc[mf][nf][0] + bias[nb];
            const float v01 = acc[mf][nf][1] + bias[nb + 1];
            const float v10 = acc[mf][nf][2] + bias[nb];
            const float v11 = acc[mf][nf][3] + bias[nb + 1];
            if (split_mode) {
                // m -> (b = m>>11, s = m&2047); n -> (d = n>>4, h = n&15)
#pragma unroll
                for (int e = 0; e < 4; e++) {
                    const int m = (e < 2) ? m_lo : m_hi;
                    const int n = nb + (e & 1);
                    const float v = (e == 0) ? v00 : (e == 1) ? v01 : (e == 2) ? v10 : v11;
                    const int b = m >> 11, s = m & 2047;
                    const int d = n >> 4,  h = n & 15;
                    C[((((size_t)b * HH + h) * SS + s) << 6) + d] = v;
                }
            } else {
                *(float2*)&C[(size_t)m_lo * N + nb] = make_float2(v00, v01);
                *(float2*)&C[(size_t)m_hi * N + nb] = make_float2(v10, v11);
            }
        }
    }
}

// ---------------------------------------------------------------------------
// Flash attention (fp32, causal). One CTA = 64 queries of one (b,h).
// Unchanged from round 2 (next optimization target).
// ---------------------------------------------------------------------------
#define FA_SM_FLOATS (64*64 + 64*65 + 64*64 + 64*64)   // Qs, Kst, Vs, Ps
#define FA_SM_BYTES  (FA_SM_FLOATS * 4)

__global__ __launch_bounds__(256) void flash_kernel(
    const float* __restrict__ Qg, const float* __restrict__ Kg,
    const float* __restrict__ Vg, float* __restrict__ Out)
{
    extern __shared__ float sm[];
    float* Qs  = sm;                       // [64][64] row-major (m,d)
    float* Kst = sm + 64 * 64;             // [64][65]  (d, n) padded
    float* Vs  = Kst + 64 * 65;            // [64][64]  (n, d)
    float* Ps  = Vs + 64 * 64;             // [64][64]  (m, n)

    const int tid = threadIdx.x;
    const int qb  = blockIdx.x;            // query block 0..31
    const int bh  = blockIdx.y;            // 0..63
    const int b   = bh >> 4, h = bh & 15;
    const int ty  = tid >> 4, tx = tid & 15;
    const int ty4 = ty * 4,  tx4 = tx * 4;

    const float* q = Qg + (size_t)bh * SS * DK;
    const float* k = Kg + (size_t)bh * SS * DK;
    const float* v = Vg + (size_t)bh * SS * DK;

    for (int idx = tid; idx < 64 * 16; idx += 256) {
        const int r = idx >> 4, c = (idx & 15) << 2;
        *(float4*)&Qs[r * 64 + c] =
            *(const float4*)&q[(size_t)(qb * 64 + r) * DK + c];
    }

    const float NEG = -1e30f;
    float m_i[4], l_i[4], o[4][4];
#pragma unroll
    for (int i = 0; i < 4; i++) {
        m_i[i] = NEG; l_i[i] = 0.0f;
#pragma unroll
        for (int j = 0; j < 4; j++) o[i][j] = 0.0f;
    }

    for (int jb = 0; jb <= qb; jb++) {
        __syncthreads();
        for (int idx = tid; idx < 64 * 16; idx += 256) {
            const int r = idx >> 4, c = (idx & 15) << 2;
            float4 kv = *(const float4*)&k[(size_t)(jb * 64 + r) * DK + c];
            Kst[(c + 0) * 65 + r] = kv.x;
            Kst[(c + 1) * 65 + r] = kv.y;
            Kst[(c + 2) * 65 + r] = kv.z;
            Kst[(c + 3) * 65 + r] = kv.w;
            *(float4*)&Vs[r * 64 + c] =
                *(const float4*)&v[(size_t)(jb * 64 + r) * DK + c];
        }
        __syncthreads();

        float sv[4][4];
#pragma unroll
        for (int i = 0; i < 4; i++)
#pragma unroll
            for (int j = 0; j < 4; j++) sv[i][j] = 0.0f;

#pragma unroll 8
        for (int d = 0; d < 64; d++) {
            float a0 = Qs[(ty4 + 0) * 64 + d];
            float a1 = Qs[(ty4 + 1) * 64 + d];
            float a2 = Qs[(ty4 + 2) * 64 + d];
            float a3 = Qs[(ty4 + 3) * 64 + d];
            float b0 = Kst[d * 65 + tx4 + 0];
            float b1 = Kst[d * 65 + tx4 + 1];
            float b2 = Kst[d * 65 + tx4 + 2];
            float b3 = Kst[d * 65 + tx4 + 3];
            sv[0][0] = fmaf(a0, b0, sv[0][0]); sv[0][1] = fmaf(a0, b1, sv[0][1]);
            sv[0][2] = fmaf(a0, b2, sv[0][2]); sv[0][3] = fmaf(a0, b3, sv[0][3]);
            sv[1][0] = fmaf(a1, b0, sv[1][0]); sv[1][1] = fmaf(a1, b1, sv[1][1]);
            sv[1][2] = fmaf(a1, b2, sv[1][2]); sv[1][3] = fmaf(a1, b3, sv[1][3]);
            sv[2][0] = fmaf(a2, b0, sv[2][0]); sv[2][1] = fmaf(a2, b1, sv[2][1]);
            sv[2][2] = fmaf(a2, b2, sv[2][2]); sv[2][3] = fmaf(a2, b3, sv[2][3]);
            sv[3][0] = fmaf(a3, b0, sv[3][0]); sv[3][1] = fmaf(a3, b1, sv[3][1]);
            sv[3][2] = fmaf(a3, b2, sv[3][2]); sv[3][3] = fmaf(a3, b3, sv[3][3]);
        }

        const float scale = 0.125f;   // 1/sqrt(64)
        const bool diag = (jb == qb);
        const int gm0 = qb * 64 + ty4;
        const int gn0 = jb * 64 + tx4;

#pragma unroll
        for (int i = 0; i < 4; i++) {
#pragma unroll
            for (int j = 0; j < 4; j++) {
                float val = sv[i][j] * scale;
                if (diag && (gn0 + j > gm0 + i)) val = NEG;
                sv[i][j] = val;
            }
            float r = fmaxf(fmaxf(sv[i][0], sv[i][1]), fmaxf(sv[i][2], sv[i][3]));
            r = fmaxf(r, __shfl_xor_sync(0xffffffffu, r, 8));
            r = fmaxf(r, __shfl_xor_sync(0xffffffffu, r, 4));
            r = fmaxf(r, __shfl_xor_sync(0xffffffffu, r, 2));
            r = fmaxf(r, __shfl_xor_sync(0xffffffffu, r, 1));
            const float mn = fmaxf(m_i[i], r);
            const float corr = __expf(m_i[i] - mn);
            float rs = 0.0f;
#pragma unroll
            for (int j = 0; j < 4; j++) {
                float p = __expf(sv[i][j] - mn);
                sv[i][j] = p;
                rs += p;
            }
            rs += __shfl_xor_sync(0xffffffffu, rs, 8);
            rs += __shfl_xor_sync(0xffffffffu, rs, 4);
            rs += __shfl_xor_sync(0xffffffffu, rs, 2);
            rs += __shfl_xor_sync(0xffffffffu, rs, 1);
            l_i[i] = l_i[i] * corr + rs;
            m_i[i] = mn;
#pragma unroll
            for (int j = 0; j < 4; j++) o[i][j] *= corr;
            *(float4*)&Ps[(ty4 + i) * 64 + tx4] =
                make_float4(sv[i][0], sv[i][1], sv[i][2], sv[i][3]);
        }
        __syncthreads();

#pragma unroll 8
        for (int n = 0; n < 64; n++) {
            float4 bb = *(const float4*)&Vs[n * 64 + tx4];
            float a0 = Ps[(ty4 + 0) * 64 + n];
            float a1 = Ps[(ty4 + 1) * 64 + n];
            float a2 = Ps[(ty4 + 2) * 64 + n];
            float a3 = Ps[(ty4 + 3) * 64 + n];
            o[0][0] = fmaf(a0, bb.x, o[0][0]); o[0][1] = fmaf(a0, bb.y, o[0][1]);
            o[0][2] = fmaf(a0, bb.z, o[0][2]); o[0][3] = fmaf(a0, bb.w, o[0][3]);
            o[1][0] = fmaf(a1, bb.x, o[1][0]); o[1][1] = fmaf(a1, bb.y, o[1][1]);
            o[1][2] = fmaf(a1, bb.z, o[1][2]); o[1][3] = fmaf(a1, bb.w, o[1][3]);
            o[2][0] = fmaf(a2, bb.x, o[2][0]); o[2][1] = fmaf(a2, bb.y, o[2][1]);
            o[2][2] = fmaf(a2, bb.z, o[2][2]); o[2][3] = fmaf(a2, bb.w, o[2][3]);
            o[3][0] = fmaf(a3, bb.x, o[3][0]); o[3][1] = fmaf(a3, bb.y, o[3][1]);
            o[3][2] = fmaf(a3, bb.z, o[3][2]); o[3][3] = fmaf(a3, bb.w, o[3][3]);
        }
    }

#pragma unroll
    for (int i = 0; i < 4; i++) {
        const float inv = 1.0f / l_i[i];
        const int gm = qb * 64 + ty4 + i;
        float4 r = make_float4(o[i][0] * inv, o[i][1] * inv,
                               o[i][2] * inv, o[i][3] * inv);
        *(float4*)&Out[(((size_t)(b * SS + gm)) << 10) + h * 64 + tx4] = r;
    }
}

// ---------------------------------------------------------------------------
// Launch
// ---------------------------------------------------------------------------
extern "C" void kernel_launch(void* const* d_in, const int* in_sizes, int n_in,
                              void* d_out, int out_size)
{
    const float* query = (const float*)d_in[0];
    const float* key   = (const float*)d_in[1];
    const float* value = (const float*)d_in[2];
    // d_in[3] = mask (known causal; handled analytically)
    const float* w_q = (const float*)d_in[4];
    const float* b_q = (const float*)d_in[5];
    const float* w_k = (const float*)d_in[6];
    const float* b_k = (const float*)d_in[7];
    const float* w_v = (const float*)d_in[8];
    const float* b_v = (const float*)d_in[9];
    const float* w_o = (const float*)d_in[10];
    const float* b_o = (const float*)d_in[11];
    float* out = (float*)d_out;

    float *pq, *pk, *pv, *pa;
    cudaGetSymbolAddress((void**)&pq, g_q);
    cudaGetSymbolAddress((void**)&pk, g_k);
    cudaGetSymbolAddress((void**)&pv, g_v);
    cudaGetSymbolAddress((void**)&pa, g_att);

    cudaFuncSetAttribute(flash_kernel,
                         cudaFuncAttributeMaxDynamicSharedMemorySize,
                         FA_SM_BYTES);

    const dim3 gg(DD / 128, MM / 128);   // (8, 64) = 512 CTAs
    tgemm_nt_kernel<<<gg, 256>>>(query, w_q, b_q, pq, MM, DD, DD, 1);
    tgemm_nt_kernel<<<gg, 256>>>(key,   w_k, b_k, pk, MM, DD, DD, 1);
    tgemm_nt_kernel<<<gg, 256>>>(value, w_v, b_v, pv, MM, DD, DD, 1);

    flash_kernel<<<dim3(SS / 64, BB * HH), 256, FA_SM_BYTES>>>(pq, pk, pv, pa);

    tgemm_nt_kernel<<<gg, 256>>>(pa, w_o, b_o, out, MM, DD, DD, 0);
}